// round 9
// baseline (speedup 1.0000x reference)
#include <cuda_runtime.h>
#include <cuda_fp16.h>

#define BATCH 8
#define LEN   2048
#define EMB   512
#define NQ    8
#define IT    16     // i-rows per attn block
#define JPT   4      // j-columns per thread
#define THR   512    // attn block size
#define NCHUNK 4     // pipeline chunks (2 batches each)

// dynamic smem for the tanh buffer: THR*IT*8 bytes = 64 KB
#define SMEM_TH_BYTES (THR * IT * 8)

// scratch for rot = x @ rotation : (8, 2048, 8) fp32 = 512 KB (L2-resident)
__device__ float g_rot[BATCH * LEN * NQ];

__device__ __forceinline__ float tanh_fast(float x) {
    float y;
    asm("tanh.approx.f32 %0, %1;" : "=f"(y) : "f"(x));
    return y;
}
__device__ __forceinline__ unsigned int h2_to_u(__half2 h) {
    return *reinterpret_cast<unsigned int*>(&h);
}
__device__ __forceinline__ __half2 u_to_h2(unsigned int u) {
    return *reinterpret_cast<__half2*>(&u);
}

// ---------------------------------------------------------------------------
// Kernel 1: rot[b,l,q] = sum_e x[b,l,e] * rotation[e,q]  (row range chunked)
// 256 threads/block; each warp computes 2 rows; all 8 row-loads (LDG.128)
// issued up-front (MLP=8). Swap-butterfly reduction (17 SHFL), lanes 0..15
// store coalesced.
// ---------------------------------------------------------------------------
__global__ __launch_bounds__(256) void rot_kernel(const float* __restrict__ x,
                                                  const float* __restrict__ rotation,
                                                  int row_off)
{
    __shared__ float4 srotT4[NQ][EMB / 4];   // transposed rotation, 16 KB
    const int tid = threadIdx.x;

    float* srot = reinterpret_cast<float*>(srotT4);
    for (int idx = tid; idx < EMB * NQ; idx += 256) {
        int e = idx >> 3;
        int q = idx & 7;
        srot[q * EMB + e] = rotation[idx];
    }
    __syncthreads();

    const int warp = tid >> 5;
    const int lane = tid & 31;
    const int row0 = row_off + (blockIdx.x * 8 + warp) * 2;   // 2 rows per warp

    float4 xv[2][4];
#pragma unroll
    for (int r = 0; r < 2; r++)
#pragma unroll
        for (int k = 0; k < 4; k++)
            xv[r][k] = reinterpret_cast<const float4*>(
                x + (size_t)(row0 + r) * EMB)[k * 32 + lane];

    float a[16];   // a[o], o = r*8+q
#pragma unroll
    for (int o = 0; o < 16; o++) a[o] = 0.0f;

#pragma unroll
    for (int k = 0; k < 4; k++) {
#pragma unroll
        for (int q = 0; q < NQ; q++) {
            const float4 rq = srotT4[q][k * 32 + lane];
#pragma unroll
            for (int r = 0; r < 2; r++) {
                float& acc = a[r * 8 + q];
                acc = fmaf(xv[r][k].x, rq.x, acc);
                acc = fmaf(xv[r][k].y, rq.y, acc);
                acc = fmaf(xv[r][k].z, rq.z, acc);
                acc = fmaf(xv[r][k].w, rq.w, acc);
            }
        }
    }

#pragma unroll
    for (int off = 8; off >= 1; off >>= 1) {
#pragma unroll
        for (int t = 0; t < 8; t++) {
            if (t < off) {
                const bool hi = (lane & off) != 0;
                const float give = hi ? a[t] : a[t + off];
                const float keep = hi ? a[t + off] : a[t];
                a[t] = keep + __shfl_xor_sync(0xffffffffu, give, off);
            }
        }
    }
    a[0] += __shfl_xor_sync(0xffffffffu, a[0], 16);

    if (lane < 16)
        g_rot[(size_t)row0 * NQ + lane] = a[0];
}

// swap-butterfly reduce of 8 per-row partials within a warp.
// After: every lane holds the full-warp sum for row (lane & 7).
__device__ __forceinline__ void butterfly8(float a[8], int lane) {
#pragma unroll
    for (int off = 4; off >= 1; off >>= 1) {
#pragma unroll
        for (int t = 0; t < 4; t++) {
            if (t < off) {
                const bool hi = (lane & off) != 0;
                const float give = hi ? a[t] : a[t + off];
                const float keep = hi ? a[t + off] : a[t];
                a[t] = keep + __shfl_xor_sync(0xffffffffu, give, off);
            }
        }
    }
    a[0] += __shfl_xor_sync(0xffffffffu, a[0], 8);
    a[0] += __shfl_xor_sync(0xffffffffu, a[0], 16);
}

// ---------------------------------------------------------------------------
// Kernel 2: scores[b,i,j] = sigmoid(rot_i . rot_j) / row_sum   (batch chunked)
//   sigmoid(s) = 0.5 + 0.5*tanh(0.5*s)   (0.5 folded into qi)
//   row_sum    = 1024 + 0.5*sum_j tanh   ->  out = fmaf(t, h, h), h = 0.5/row_sum
// Block = 512 threads, IT=16, JPT=4. tanh buffer in 64 KB dynamic smem
// (uint2 per (i,thread), conflict-free STS.64/LDS.64); row-partial reduce in
// two 8-row batches (live a[8]) -> 64 regs -> 2 blocks/SM.
// ---------------------------------------------------------------------------
__global__ __launch_bounds__(THR, 2) void attn_kernel(float* __restrict__ out,
                                                      int boff)
{
    extern __shared__ uint2 s_th[];     // [i*THR + tid]  (64 KB)
    __shared__ float s_q[IT * NQ];      // 0.5 * qi rows
    __shared__ float s_part[IT][16];
    __shared__ float s_h[IT];

    const int b    = boff + blockIdx.y;
    const int i0   = blockIdx.x * IT;
    const int tid  = threadIdx.x;
    const int warp = tid >> 5;
    const int lane = tid & 31;

    if (tid < IT * NQ)
        s_q[tid] = 0.5f * g_rot[((size_t)b * LEN + i0) * NQ + tid];

    // this thread's 4 j-rows (128B contiguous): 8 x LDG.128, MLP = 8
    const float4* rj = reinterpret_cast<const float4*>(
        &g_rot[((size_t)b * LEN + tid * JPT) * NQ]);
    float4 v0[JPT], v1[JPT];
#pragma unroll
    for (int r = 0; r < JPT; r++) {
        v0[r] = __ldg(rj + r * 2 + 0);
        v1[r] = __ldg(rj + r * 2 + 1);
    }

    __syncthreads();

    const float4* sq4 = reinterpret_cast<const float4*>(s_q);
    float a[8];

#pragma unroll
    for (int half = 0; half < 2; half++) {
#pragma unroll
        for (int u = 0; u < 8; u++) {
            const int i = half * 8 + u;
            const float4 q0 = sq4[i * 2 + 0];   // broadcast LDS.128
            const float4 q1 = sq4[i * 2 + 1];
            float t[JPT];
#pragma unroll
            for (int r = 0; r < JPT; r++) {
                float s0 = v0[r].x * q0.x;
                float s1 = v1[r].x * q1.x;
                s0 = fmaf(v0[r].y, q0.y, s0);
                s1 = fmaf(v1[r].y, q1.y, s1);
                s0 = fmaf(v0[r].z, q0.z, s0);
                s1 = fmaf(v1[r].z, q1.z, s1);
                s0 = fmaf(v0[r].w, q0.w, s0);
                s1 = fmaf(v1[r].w, q1.w, s1);
                t[r] = tanh_fast(s0 + s1);
            }
            a[u] = (t[0] + t[1]) + (t[2] + t[3]);
            uint2 u2;
            u2.x = h2_to_u(__floats2half2_rn(t[0], t[1]));
            u2.y = h2_to_u(__floats2half2_rn(t[2], t[3]));
            s_th[i * THR + tid] = u2;           // STS.64, conflict-free
        }
        butterfly8(a, lane);
        if (lane < 8)
            s_part[half * 8 + lane][warp] = a[0];
    }

    __syncthreads();

    // second level: warp w (16 warps) reduces row w's 16 warp-partials
    {
        float p = (lane < 16) ? s_part[warp][lane] : 0.0f;
#pragma unroll
        for (int off = 8; off >= 1; off >>= 1)
            p += __shfl_xor_sync(0xffffffffu, p, off);
        if (lane == 0)
            s_h[warp] = __fdividef(0.5f, fmaf(0.5f, p, 1024.0f));
    }
    __syncthreads();

    float4* obase = reinterpret_cast<float4*>(
        out + ((size_t)(b * LEN + i0)) * LEN) + tid;
#pragma unroll
    for (int i = 0; i < IT; i++) {
        const float h = s_h[i];
        const uint2 u2 = s_th[i * THR + tid];   // LDS.64, conflict-free
        const float2 lo = __half22float2(u_to_h2(u2.x));
        const float2 hi = __half22float2(u_to_h2(u2.y));
        float4 o;
        o.x = fmaf(lo.x, h, h);
        o.y = fmaf(lo.y, h, h);
        o.z = fmaf(hi.x, h, h);
        o.w = fmaf(hi.y, h, h);
        __stcs(obase, o);                       // evict-first streaming STG.128
        obase += LEN / 4;
    }
}

// ---------------------------------------------------------------------------
// Pipelined launch: rot chunks serial on the main (capture) stream; attn
// chunk k runs on a side stream gated by an event recorded after rot chunk k,
// so rot chunks 2..4 overlap earlier attn chunks. Graph-capture-safe
// fork/join via events; streams/events created once (no device allocations).
// ---------------------------------------------------------------------------
extern "C" void kernel_launch(void* const* d_in, const int* in_sizes, int n_in,
                              void* d_out, int out_size)
{
    const float* x        = (const float*)d_in[0];   // (8, 2048, 512)
    const float* rotation = (const float*)d_in[1];   // (512, 8)
    float* out = (float*)d_out;                      // (8, 2048, 2048)

    static cudaStream_t s1;
    static cudaEvent_t  ev_rot[NCHUNK];
    static cudaEvent_t  ev_join;
    static int init = 0;
    if (!init) {
        cudaFuncSetAttribute(attn_kernel,
                             cudaFuncAttributeMaxDynamicSharedMemorySize,
                             SMEM_TH_BYTES);
        cudaStreamCreateWithFlags(&s1, cudaStreamNonBlocking);
        for (int k = 0; k < NCHUNK; k++)
            cudaEventCreateWithFlags(&ev_rot[k], cudaEventDisableTiming);
        cudaEventCreateWithFlags(&ev_join, cudaEventDisableTiming);
        init = 1;
    }

    const int rows_per_chunk    = (BATCH / NCHUNK) * LEN;   // 4096
    const int rot_blocks        = rows_per_chunk / 16;      // 256
    const int batches_per_chunk = BATCH / NCHUNK;           // 2

    for (int k = 0; k < NCHUNK; k++) {
        // rot chunk k on the main stream (serial chain of rot chunks)
        rot_kernel<<<rot_blocks, 256, 0, 0>>>(x, rotation, k * rows_per_chunk);
        cudaEventRecord(ev_rot[k], 0);
        // attn chunk k on the side stream, gated on rot chunk k
        cudaStreamWaitEvent(s1, ev_rot[k], 0);
        dim3 grid(LEN / IT, batches_per_chunk);
        attn_kernel<<<grid, THR, SMEM_TH_BYTES, s1>>>(out, k * batches_per_chunk);
    }

    // join side stream back into the main stream
    cudaEventRecord(ev_join, s1);
    cudaStreamWaitEvent(0, ev_join, 0);
}

// round 10
// speedup vs baseline: 1.3672x; 1.3672x over previous
#include <cuda_runtime.h>
#include <cuda_fp16.h>

#define BATCH 8
#define LEN   2048
#define EMB   512
#define NQ    8
#define IT    16     // i-rows per attn block
#define JPT   4      // j-columns per thread
#define THR   512    // attn block size

// dynamic smem for the tanh buffer: THR*IT*8 bytes = 64 KB
#define SMEM_TH_BYTES (THR * IT * 8)

// scratch for rot = x @ rotation : (8, 2048, 8) fp32 = 512 KB (L2-resident)
__device__ float g_rot[BATCH * LEN * NQ];

__device__ __forceinline__ float tanh_fast(float x) {
    float y;
    asm("tanh.approx.f32 %0, %1;" : "=f"(y) : "f"(x));
    return y;
}
__device__ __forceinline__ unsigned int h2_to_u(__half2 h) {
    return *reinterpret_cast<unsigned int*>(&h);
}
__device__ __forceinline__ __half2 u_to_h2(unsigned int u) {
    return *reinterpret_cast<__half2*>(&u);
}

// ---------------------------------------------------------------------------
// Kernel 1: rot[b,l,q] = sum_e x[b,l,e] * rotation[e,q]
// 512 blocks x 256 threads. Each warp computes 4 rows; all 16 row-chunk
// loads (LDG.128) issued up-front (MLP=16). Full 5-stage swap-butterfly
// reduces the 32 accumulators across 32 lanes: lane l ends holding the
// fully-reduced element (row = l>>3, q = l&7) -> every lane stores, one
// contiguous 128B STG per warp.
// ---------------------------------------------------------------------------
__global__ __launch_bounds__(256) void rot_kernel(const float* __restrict__ x,
                                                  const float* __restrict__ rotation)
{
    __shared__ float4 srotT4[NQ][EMB / 4];   // transposed rotation, 16 KB
    const int tid = threadIdx.x;

    float* srot = reinterpret_cast<float*>(srotT4);
    for (int idx = tid; idx < EMB * NQ; idx += 256) {
        int e = idx >> 3;
        int q = idx & 7;
        srot[q * EMB + e] = rotation[idx];
    }
    __syncthreads();

    const int warp = tid >> 5;
    const int lane = tid & 31;
    const int row0 = (blockIdx.x * 8 + warp) * 4;   // 4 rows per warp

    // issue all 16 global loads first (4 rows x 4 chunks), MLP = 16
    float4 xv[4][4];
#pragma unroll
    for (int r = 0; r < 4; r++)
#pragma unroll
        for (int k = 0; k < 4; k++)
            xv[r][k] = reinterpret_cast<const float4*>(
                x + (size_t)(row0 + r) * EMB)[k * 32 + lane];

    float a[32];   // a[o], o = r*8+q
#pragma unroll
    for (int o = 0; o < 32; o++) a[o] = 0.0f;

#pragma unroll
    for (int k = 0; k < 4; k++) {
#pragma unroll
        for (int q = 0; q < NQ; q++) {
            const float4 rq = srotT4[q][k * 32 + lane];
#pragma unroll
            for (int r = 0; r < 4; r++) {
                float& acc = a[r * 8 + q];
                acc = fmaf(xv[r][k].x, rq.x, acc);
                acc = fmaf(xv[r][k].y, rq.y, acc);
                acc = fmaf(xv[r][k].z, rq.z, acc);
                acc = fmaf(xv[r][k].w, rq.w, acc);
            }
        }
    }

    // full swap-butterfly: stages 16,8,4,2,1. After stage off, lane l's
    // array of length off holds sums over lane-groups; at the end lane l
    // holds the fully reduced a[l].
#pragma unroll
    for (int off = 16; off >= 1; off >>= 1) {
#pragma unroll
        for (int t = 0; t < 16; t++) {
            if (t < off) {
                const bool hi = (lane & off) != 0;
                const float give = hi ? a[t] : a[t + off];
                const float keep = hi ? a[t + off] : a[t];
                a[t] = keep + __shfl_xor_sync(0xffffffffu, give, off);
            }
        }
    }

    // lane l stores element (row = l>>3, q = l&7): contiguous 128B per warp
    g_rot[(size_t)row0 * NQ + lane] = a[0];
}

// swap-butterfly reduce of 8 per-row partials within a warp.
// After: every lane holds the full-warp sum for row (lane & 7).
__device__ __forceinline__ void butterfly8(float a[8], int lane) {
#pragma unroll
    for (int off = 4; off >= 1; off >>= 1) {
#pragma unroll
        for (int t = 0; t < 4; t++) {
            if (t < off) {
                const bool hi = (lane & off) != 0;
                const float give = hi ? a[t] : a[t + off];
                const float keep = hi ? a[t + off] : a[t];
                a[t] = keep + __shfl_xor_sync(0xffffffffu, give, off);
            }
        }
    }
    a[0] += __shfl_xor_sync(0xffffffffu, a[0], 8);
    a[0] += __shfl_xor_sync(0xffffffffu, a[0], 16);
}

// ---------------------------------------------------------------------------
// Kernel 2: scores[b,i,j] = sigmoid(rot_i . rot_j) / row_sum
//   sigmoid(s) = 0.5 + 0.5*tanh(0.5*s)   (0.5 folded into qi)
//   row_sum    = 1024 + 0.5*sum_j tanh   ->  out = fmaf(t, h, h), h = 0.5/row_sum
// Block = 512 threads, IT=16, JPT=4, grid (128, 8). tanh buffer in 64 KB
// dynamic smem (uint2 per (i,thread), conflict-free STS.64/LDS.64);
// row-partial reduce in two 8-row batches (live a[8]) -> 64 regs ->
// 2 blocks/SM co-resident. (R8 form — unchanged.)
// ---------------------------------------------------------------------------
__global__ __launch_bounds__(THR, 2) void attn_kernel(float* __restrict__ out)
{
    extern __shared__ uint2 s_th[];     // [i*THR + tid]  (64 KB)
    __shared__ float s_q[IT * NQ];      // 0.5 * qi rows
    __shared__ float s_part[IT][16];
    __shared__ float s_h[IT];

    const int b    = blockIdx.y;
    const int i0   = blockIdx.x * IT;
    const int tid  = threadIdx.x;
    const int warp = tid >> 5;
    const int lane = tid & 31;

    if (tid < IT * NQ)
        s_q[tid] = 0.5f * g_rot[((size_t)b * LEN + i0) * NQ + tid];

    // this thread's 4 j-rows (128B contiguous): 8 x LDG.128, MLP = 8
    const float4* rj = reinterpret_cast<const float4*>(
        &g_rot[((size_t)b * LEN + tid * JPT) * NQ]);
    float4 v0[JPT], v1[JPT];
#pragma unroll
    for (int r = 0; r < JPT; r++) {
        v0[r] = __ldg(rj + r * 2 + 0);
        v1[r] = __ldg(rj + r * 2 + 1);
    }

    __syncthreads();

    const float4* sq4 = reinterpret_cast<const float4*>(s_q);
    float a[8];

#pragma unroll
    for (int half = 0; half < 2; half++) {
#pragma unroll
        for (int u = 0; u < 8; u++) {
            const int i = half * 8 + u;
            const float4 q0 = sq4[i * 2 + 0];   // broadcast LDS.128
            const float4 q1 = sq4[i * 2 + 1];
            float t[JPT];
#pragma unroll
            for (int r = 0; r < JPT; r++) {
                float s0 = v0[r].x * q0.x;
                float s1 = v1[r].x * q1.x;
                s0 = fmaf(v0[r].y, q0.y, s0);
                s1 = fmaf(v1[r].y, q1.y, s1);
                s0 = fmaf(v0[r].z, q0.z, s0);
                s1 = fmaf(v1[r].z, q1.z, s1);
                s0 = fmaf(v0[r].w, q0.w, s0);
                s1 = fmaf(v1[r].w, q1.w, s1);
                t[r] = tanh_fast(s0 + s1);
            }
            a[u] = (t[0] + t[1]) + (t[2] + t[3]);
            uint2 u2;
            u2.x = h2_to_u(__floats2half2_rn(t[0], t[1]));
            u2.y = h2_to_u(__floats2half2_rn(t[2], t[3]));
            s_th[i * THR + tid] = u2;           // STS.64, conflict-free
        }
        butterfly8(a, lane);
        if (lane < 8)
            s_part[half * 8 + lane][warp] = a[0];
    }

    __syncthreads();

    // second level: warp w (16 warps) reduces row w's 16 warp-partials
    {
        float p = (lane < 16) ? s_part[warp][lane] : 0.0f;
#pragma unroll
        for (int off = 8; off >= 1; off >>= 1)
            p += __shfl_xor_sync(0xffffffffu, p, off);
        if (lane == 0)
            s_h[warp] = __fdividef(0.5f, fmaf(0.5f, p, 1024.0f));
    }
    __syncthreads();

    float4* obase = reinterpret_cast<float4*>(
        out + ((size_t)(b * LEN + i0)) * LEN) + tid;
#pragma unroll
    for (int i = 0; i < IT; i++) {
        const float h = s_h[i];
        const uint2 u2 = s_th[i * THR + tid];   // LDS.64, conflict-free
        const float2 lo = __half22float2(u_to_h2(u2.x));
        const float2 hi = __half22float2(u_to_h2(u2.y));
        float4 o;
        o.x = fmaf(lo.x, h, h);
        o.y = fmaf(lo.y, h, h);
        o.z = fmaf(hi.x, h, h);
        o.w = fmaf(hi.y, h, h);
        __stcs(obase, o);                       // evict-first streaming STG.128
        obase += LEN / 4;
    }
}

extern "C" void kernel_launch(void* const* d_in, const int* in_sizes, int n_in,
                              void* d_out, int out_size)
{
    const float* x        = (const float*)d_in[0];   // (8, 2048, 512)
    const float* rotation = (const float*)d_in[1];   // (512, 8)
    float* out = (float*)d_out;                      // (8, 2048, 2048)

    static int init = 0;
    if (!init) {
        cudaFuncSetAttribute(attn_kernel,
                             cudaFuncAttributeMaxDynamicSharedMemorySize,
                             SMEM_TH_BYTES);
        init = 1;
    }

    rot_kernel<<<512, 256>>>(x, rotation);

    dim3 grid(LEN / IT, BATCH);                      // (128, 8)
    attn_kernel<<<grid, THR, SMEM_TH_BYTES>>>(out);
}